// round 7
// baseline (speedup 1.0000x reference)
#include <cuda_runtime.h>
#include <cuda_fp16.h>
#include <mma.h>
#include <math.h>

using namespace nvcuda;

#define NN   50000
#define NE   800000
#define ET   850000
#define FIN  128
#define HID  64
#define NG   512
#define SLOPE 0.2f
#define NCHUNK 196                 // ceil(NN/256)
#define NTILE  391                 // ceil(NN/128)
#define SMEM_BYTES 53248           // B tile 18432 + A/C tile 34816

// ---------------- scratch ----------------
__device__ __half g_hh[NN * HID];
__device__ __half g_out[NN * HID];
__device__ float g_asrc[NN];
__device__ float g_adst[NN];
__device__ int   g_cnt[NN];
__device__ int   g_rofs[NN];
__device__ int   g_pos[NN];
__device__ int2  g_edge[ET];
__device__ float g_pooled[NG * HID];
__device__ float g_gcnt[NG];
__device__ float g_scal[8];
__device__ int   g_bsum[256];
__device__ int   g_bpre[256];
__device__ float g_part[2048];
__device__ unsigned g_barc = 0;
__device__ unsigned g_gen  = 0;
__device__ int   g_tile;

// ---------------- software grid barrier (all blocks co-resident) ----------------
__device__ __forceinline__ void gbar(int nb) {
    __syncthreads();
    if (threadIdx.x == 0) {
        __threadfence();
        unsigned gen = *((volatile unsigned*)&g_gen);
        if (atomicAdd(&g_barc, 1u) == (unsigned)nb - 1u) {
            g_barc = 0;
            __threadfence();
            atomicAdd(&g_gen, 1u);
        } else {
            while (*((volatile unsigned*)&g_gen) == gen) __nanosleep(32);
        }
        __threadfence();
    }
    __syncthreads();
}

// ---------------- HMMA 128x64 tile GEMM + attention logits ----------------
__device__ void gemm_tile(char* sbuf, int tile, const float* __restrict__ X,
                          int ext, int Fin, const float* __restrict__ W,
                          const float* __restrict__ bprev,
                          const float* __restrict__ as_, const float* __restrict__ ad_) {
    __half* Bs = reinterpret_cast<__half*>(sbuf);            // [Fin][72]
    __half* As = reinterpret_cast<__half*>(sbuf + 18432);    // [128][136]
    float*  Cs = reinterpret_cast<float*>(sbuf + 18432);     // [128][68] alias

    int t = threadIdx.x;
    int w = t >> 5;
    int n0 = tile * 128;
    int r = t >> 1;
    int n = n0 + r;

    if (ext) {
        const float4* xr = reinterpret_cast<const float4*>(X + (size_t)n * FIN);
        #pragma unroll
        for (int f = 0; f < 16; f++) {
            int c4 = (t & 1) * 16 + f;
            float4 v = (n < NN) ? xr[c4] : make_float4(0, 0, 0, 0);
            __half2* p = reinterpret_cast<__half2*>(&As[r * 136 + c4 * 4]);
            p[0] = __floats2half2_rn(v.x, v.y);
            p[1] = __floats2half2_rn(v.z, v.w);
        }
    } else {
        int cb = (t & 1) * 32;
        #pragma unroll
        for (int c = 0; c < 16; c++) {
            int col = cb + c * 2;
            float2 hv = {0.f, 0.f};
            if (n < NN)
                hv = __half22float2(*reinterpret_cast<const __half2*>(
                    &g_out[((size_t)n << 6) + col]));
            hv.x = fmaxf(hv.x + bprev[col], 0.f);
            hv.y = fmaxf(hv.y + bprev[col + 1], 0.f);
            *reinterpret_cast<__half2*>(&As[r * 136 + col]) = __floats2half2_rn(hv.x, hv.y);
        }
    }
    {
        int tot4 = Fin * HID / 4;
        const float4* w4 = reinterpret_cast<const float4*>(W);
        for (int idx = t; idx < tot4; idx += 256) {
            int rr = idx >> 4, c4 = idx & 15;
            float4 v = w4[idx];
            __half2* p = reinterpret_cast<__half2*>(&Bs[rr * 72 + c4 * 4]);
            p[0] = __floats2half2_rn(v.x, v.y);
            p[1] = __floats2half2_rn(v.z, v.w);
        }
    }
    __syncthreads();

    wmma::fragment<wmma::accumulator, 16, 16, 16, float> acc[4];
    #pragma unroll
    for (int nt = 0; nt < 4; nt++) wmma::fill_fragment(acc[nt], 0.f);
    int ks = Fin >> 4;
    for (int kt = 0; kt < ks; kt++) {
        wmma::fragment<wmma::matrix_a, 16, 16, 16, __half, wmma::row_major> af;
        wmma::load_matrix_sync(af, &As[(w * 16) * 136 + kt * 16], 136);
        #pragma unroll
        for (int nt = 0; nt < 4; nt++) {
            wmma::fragment<wmma::matrix_b, 16, 16, 16, __half, wmma::row_major> bf;
            wmma::load_matrix_sync(bf, &Bs[(kt * 16) * 72 + nt * 16], 72);
            wmma::mma_sync(acc[nt], af, bf, acc[nt]);
        }
    }
    __syncthreads();
    #pragma unroll
    for (int nt = 0; nt < 4; nt++)
        wmma::store_matrix_sync(&Cs[(w * 16) * 68 + nt * 16], acc[nt], 68,
                                wmma::mem_row_major);
    __syncthreads();

    {
        int cb = (t & 1) * 32;
        float s = 0.f, d = 0.f;
        if (n < NN) {
            #pragma unroll
            for (int c = 0; c < 32; c += 2) {
                int col = cb + c;
                float v0 = Cs[r * 68 + col];
                float v1 = Cs[r * 68 + col + 1];
                *reinterpret_cast<__half2*>(&g_hh[((size_t)n << 6) + col]) =
                    __floats2half2_rn(v0, v1);
                s = fmaf(v0, as_[col], s); s = fmaf(v1, as_[col + 1], s);
                d = fmaf(v0, ad_[col], d); d = fmaf(v1, ad_[col + 1], d);
            }
        }
        s += __shfl_xor_sync(0xffffffffu, s, 1);
        d += __shfl_xor_sync(0xffffffffu, d, 1);
        if (!(t & 1) && n < NN) { g_asrc[n] = s; g_adst[n] = d; }
    }
    __syncthreads();
}

// ---------------- segmented aggregation: warp per dst node, unroll 8 ----------------
__device__ void agg_phase(int layer, int gwid, int nwarps,
                          const int* __restrict__ batch,
                          const float* __restrict__ bias_last) {
    int lane = threadIdx.x & 31;
    float c = g_scal[1 + layer];

    for (int n = gwid; n < NN; n += nwarps) {
        int start = g_rofs[n] + g_bpre[n >> 8];
        int n2 = n + 1;
        int end = (n2 == NN) ? ET : g_rofs[n2] + g_bpre[n2 >> 8];
        float adstn = g_adst[n];

        float accx = 0.f, accy = 0.f, ssum = 0.f;

        for (int base = start; base < end; base += 32) {
            int i = base + lane;
            int s_l = 0;
            float alpha = 0.f;
            if (i < end) {
                int2 ev = g_edge[i];
                s_l = ev.x;
                float al = g_asrc[s_l] + adstn + __int_as_float(ev.y) * c;
                al = fmaxf(al, 0.f) + SLOPE * fminf(al, 0.f);
                alpha = __expf(al);
            }
            ssum += alpha;
            int cnt = min(32, end - base);
            int jj = 0;
            for (; jj + 8 <= cnt; jj += 8) {
                __half2 hv[8];
                float aj[8];
                #pragma unroll
                for (int u = 0; u < 8; u++) {
                    int sj = __shfl_sync(0xffffffffu, s_l, jj + u);
                    aj[u]  = __shfl_sync(0xffffffffu, alpha, jj + u);
                    hv[u] = *reinterpret_cast<const __half2*>(
                        &g_hh[((size_t)sj << 6) + (lane << 1)]);
                }
                #pragma unroll
                for (int u = 0; u < 8; u++) {
                    float2 f = __half22float2(hv[u]);
                    accx = fmaf(aj[u], f.x, accx);
                    accy = fmaf(aj[u], f.y, accy);
                }
            }
            for (; jj < cnt; jj++) {
                int   sj = __shfl_sync(0xffffffffu, s_l, jj);
                float a2 = __shfl_sync(0xffffffffu, alpha, jj);
                float2 f = __half22float2(*reinterpret_cast<const __half2*>(
                    &g_hh[((size_t)sj << 6) + (lane << 1)]));
                accx = fmaf(a2, f.x, accx);
                accy = fmaf(a2, f.y, accy);
            }
        }

        #pragma unroll
        for (int off = 16; off > 0; off >>= 1)
            ssum += __shfl_xor_sync(0xffffffffu, ssum, off);
        float inv = 1.f / (ssum + 1e-16f);
        float ox = accx * inv, oy = accy * inv;

        if (layer < 2) {
            *reinterpret_cast<__half2*>(&g_out[((size_t)n << 6) + (lane << 1)]) =
                __floats2half2_rn(ox, oy);
        } else {
            int g = batch[n];
            float2 bb = *reinterpret_cast<const float2*>(&bias_last[lane << 1]);
            float* p = &g_pooled[((size_t)g << 6) + (lane << 1)];
            asm volatile("red.global.add.v2.f32 [%0], {%1,%2};"
                         :: "l"(p), "f"(ox + bb.x), "f"(oy + bb.y) : "memory");
            if (lane == 0) atomicAdd(&g_gcnt[g], 1.f);
        }
    }
}

// ---------------- the mega kernel ----------------
__global__ void __launch_bounds__(256, 2) k_mega(
    const float* __restrict__ x, const int* __restrict__ eidx,
    const float* __restrict__ ew, const int* __restrict__ batch,
    const float* __restrict__ W0, const float* __restrict__ as0,
    const float* __restrict__ ad0, const float* __restrict__ We0,
    const float* __restrict__ ae0, const float* __restrict__ b0,
    const float* __restrict__ W1, const float* __restrict__ as1,
    const float* __restrict__ ad1, const float* __restrict__ We1,
    const float* __restrict__ ae1, const float* __restrict__ b1,
    const float* __restrict__ W2, const float* __restrict__ as2,
    const float* __restrict__ ad2, const float* __restrict__ We2,
    const float* __restrict__ ae2, const float* __restrict__ b2,
    const float* __restrict__ lin_w, const float* __restrict__ lin_b,
    float* __restrict__ outp) {
    extern __shared__ char sbuf[];
    __shared__ int s_tile;

    int nb = gridDim.x;
    int t = threadIdx.x;
    int gtid = blockIdx.x * 256 + t;
    int nthreads = nb * 256;
    int gwid = gtid >> 5;
    int nwarps = nthreads >> 5;

    // ---- P0: init + edge-weight partial sums ----
    for (int i = gtid; i < NN; i += nthreads) g_cnt[i] = 1;   // self-loop pre-count
    for (int i = gtid; i < NG * HID; i += nthreads) g_pooled[i] = 0.f;
    for (int i = gtid; i < NG; i += nthreads) g_gcnt[i] = 0.f;
    if (gtid == 0) g_tile = 0;
    {
        float acc = 0.f;
        for (int i = gtid; i < NE; i += nthreads) acc += ew[i];
        float* sf = reinterpret_cast<float*>(sbuf);
        sf[t] = acc;
        __syncthreads();
        for (int o = 128; o > 0; o >>= 1) {
            if (t < o) sf[t] += sf[t + o];
            __syncthreads();
        }
        if (t == 0) g_part[blockIdx.x] = sf[0];
        __syncthreads();
    }
    gbar(nb);

    // ---- P1: histogram || steal layer-1 gemm tiles ----
    for (int q = gtid; q < NE / 4; q += nthreads) {
        int4 d4 = reinterpret_cast<const int4*>(eidx + NE)[q];
        atomicAdd(&g_cnt[d4.x], 1);
        atomicAdd(&g_cnt[d4.y], 1);
        atomicAdd(&g_cnt[d4.z], 1);
        atomicAdd(&g_cnt[d4.w], 1);
    }
    while (true) {
        __syncthreads();
        if (t == 0) s_tile = atomicAdd(&g_tile, 1);
        __syncthreads();
        int tile = s_tile;
        if (tile >= NTILE) break;
        gemm_tile(sbuf, tile, x, 1, FIN, W0, b0 /*unused*/, as0, ad0);
    }
    gbar(nb);

    // ---- P2: local exclusive scans ----
    {
        int* sh = reinterpret_cast<int*>(sbuf);
        for (int cid = blockIdx.x; cid < NCHUNK; cid += nb) {
            int i = cid * 256 + t;
            int v = (i < NN) ? g_cnt[i] : 0;
            sh[t] = v;
            __syncthreads();
            for (int o = 1; o < 256; o <<= 1) {
                int xv = (t >= o) ? sh[t - o] : 0;
                __syncthreads();
                sh[t] += xv;
                __syncthreads();
            }
            if (i < NN) {
                int rr = sh[t] - v;
                g_rofs[i] = rr;
                g_pos[i] = rr;
            }
            if (t == 255) g_bsum[cid] = sh[255];
            __syncthreads();
        }
    }
    gbar(nb);

    // ---- P3: block 0: scan block sums + ew total + c scalars ----
    if (blockIdx.x == 0) {
        int* sh = reinterpret_cast<int*>(sbuf);
        int v = (t < NCHUNK) ? g_bsum[t] : 0;
        sh[t] = v;
        __syncthreads();
        for (int o = 1; o < 256; o <<= 1) {
            int xv = (t >= o) ? sh[t - o] : 0;
            __syncthreads();
            sh[t] += xv;
            __syncthreads();
        }
        if (t < NCHUNK) g_bpre[t] = sh[t] - v;
        __syncthreads();
        float* sf = reinterpret_cast<float*>(sbuf);
        float a = 0.f;
        for (int i = t; i < nb; i += 256) a += g_part[i];
        sf[t] = a;
        __syncthreads();
        for (int o = 128; o > 0; o >>= 1) {
            if (t < o) sf[t] += sf[t + o];
            __syncthreads();
        }
        if (t == 0) g_scal[0] = sf[0];
        __syncthreads();
        #pragma unroll
        for (int l = 0; l < 3; l++) {
            const float* We = (l == 0) ? We0 : (l == 1) ? We1 : We2;
            const float* ae = (l == 0) ? ae0 : (l == 1) ? ae1 : ae2;
            sf[t] = (t < HID) ? We[t] * ae[t] : 0.f;
            __syncthreads();
            for (int o = 128; o > 0; o >>= 1) {
                if (t < o) sf[t] += sf[t + o];
                __syncthreads();
            }
            if (t == 0) g_scal[1 + l] = sf[0];
            __syncthreads();
        }
    }
    gbar(nb);

    // ---- P4: CSR scatter ----
    for (int e = gtid; e < ET; e += nthreads) {
        int s, d;
        float a;
        if (e < NE) {
            s = eidx[e];
            d = eidx[NE + e];
            a = ew[e];
        } else {
            s = d = e - NE;
            a = g_scal[0] * (1.0f / (float)NE);
        }
        int p = atomicAdd(&g_pos[d], 1) + g_bpre[d >> 8];
        g_edge[p] = make_int2(s, __float_as_int(a));
    }
    gbar(nb);

    // ---- layers ----
    agg_phase(0, gwid, nwarps, batch, b2);
    gbar(nb);
    for (int tile = blockIdx.x; tile < NTILE; tile += nb)
        gemm_tile(sbuf, tile, nullptr, 0, HID, W1, b0, as1, ad1);
    gbar(nb);
    agg_phase(1, gwid, nwarps, batch, b2);
    gbar(nb);
    for (int tile = blockIdx.x; tile < NTILE; tile += nb)
        gemm_tile(sbuf, tile, nullptr, 0, HID, W2, b1, as2, ad2);
    gbar(nb);
    agg_phase(2, gwid, nwarps, batch, b2);
    gbar(nb);

    // ---- readout: warp per graph ----
    {
        int lane = t & 31;
        for (int g = gwid; g < NG; g += nwarps) {
            float cnt = fmaxf(g_gcnt[g], 1.f);
            float2 p = *reinterpret_cast<const float2*>(
                &g_pooled[((size_t)g << 6) + lane * 2]);
            float2 wv = *reinterpret_cast<const float2*>(&lin_w[lane * 2]);
            float v = p.x * wv.x + p.y * wv.y;
            #pragma unroll
            for (int o = 16; o > 0; o >>= 1)
                v += __shfl_xor_sync(0xffffffffu, v, o);
            if (lane == 0)
                outp[g] = 1.f / (1.f + expf(-(v / cnt + lin_b[0])));
        }
    }
}

// ---------------- launch ----------------
extern "C" void kernel_launch(void* const* d_in, const int* in_sizes, int n_in,
                              void* d_out, int out_size) {
    const float* x     = (const float*)d_in[0];
    const int*   eidx  = (const int*)  d_in[1];
    const float* ew    = (const float*)d_in[2];
    const int*   batch = (const int*)  d_in[3];
    const float* W0 = (const float*)d_in[4],  *as0 = (const float*)d_in[5],
               *ad0 = (const float*)d_in[6],  *We0 = (const float*)d_in[7],
               *ae0 = (const float*)d_in[8],  *b0  = (const float*)d_in[9];
    const float* W1 = (const float*)d_in[10], *as1 = (const float*)d_in[11],
               *ad1 = (const float*)d_in[12], *We1 = (const float*)d_in[13],
               *ae1 = (const float*)d_in[14], *b1  = (const float*)d_in[15];
    const float* W2 = (const float*)d_in[16], *as2 = (const float*)d_in[17],
               *ad2 = (const float*)d_in[18], *We2 = (const float*)d_in[19],
               *ae2 = (const float*)d_in[20], *b2  = (const float*)d_in[21];
    const float* lin_w = (const float*)d_in[22];
    const float* lin_b = (const float*)d_in[23];
    float* outp = (float*)d_out;

    cudaFuncSetAttribute(k_mega, cudaFuncAttributeMaxDynamicSharedMemorySize,
                         SMEM_BYTES);
    int dev = 0;
    cudaGetDevice(&dev);
    int sms = 0;
    cudaDeviceGetAttribute(&sms, cudaDevAttrMultiProcessorCount, dev);
    int occ = 0;
    cudaOccupancyMaxActiveBlocksPerMultiprocessor(&occ, k_mega, 256, SMEM_BYTES);
    if (occ < 1) occ = 1;
    long long grid = (long long)sms * occ;
    if (grid > 2048) grid = 2048;

    k_mega<<<(int)grid, 256, SMEM_BYTES>>>(
        x, eidx, ew, batch,
        W0, as0, ad0, We0, ae0, b0,
        W1, as1, ad1, We1, ae1, b1,
        W2, as2, ad2, We2, ae2, b2,
        lin_w, lin_b, outp);
}

// round 8
// speedup vs baseline: 1.3941x; 1.3941x over previous
#include <cuda_runtime.h>
#include <cuda_fp16.h>
#include <mma.h>
#include <math.h>

using namespace nvcuda;

#define NN   50000
#define NE   800000
#define ET   850000
#define FIN  128
#define HID  64
#define NG   512
#define SLOPE 0.2f
#define PRE_BLOCKS 512

// ---------------- scratch ----------------
__device__ __half g_hh[NN * HID];     // transformed features (fp16, gathered)
__device__ __half g_out[NN * HID];    // normalized layer output (fp16)
__device__ float g_asrc[NN];
__device__ float g_adst[NN];
__device__ int   g_cnt[NN];
__device__ int   g_rofs[NN];          // LOCAL exclusive scan (per 256-block)
__device__ int   g_pos[NN];
__device__ int2  g_edge[ET];          // (src, eatt bits), permuted by dst
__device__ float g_pooled[NG * HID];
__device__ float g_gcnt[NG];
__device__ float g_scal[8];           // [0]=sum(ew), [1..3]=c per layer
__device__ int   g_bsum[256];
__device__ int   g_bpre[256];
__device__ float g_part[PRE_BLOCKS];

// ---------------- fused setup ----------------
__global__ void k_pre(const float* __restrict__ We0, const float* __restrict__ ae0,
                      const float* __restrict__ We1, const float* __restrict__ ae1,
                      const float* __restrict__ We2, const float* __restrict__ ae2,
                      const float* __restrict__ ew) {
    __shared__ float sm[256];
    int b = blockIdx.x, t = threadIdx.x;
    int i = b * 256 + t;
    if (i < NN) g_cnt[i] = 1;                 // self-loop pre-counted
    if (i < NG * HID) g_pooled[i] = 0.f;
    if (i < NG) g_gcnt[i] = 0.f;

    float acc = 0.f;
    for (int idx = i; idx < NE; idx += PRE_BLOCKS * 256) acc += ew[idx];
    sm[t] = acc;
    __syncthreads();
    for (int off = 128; off > 0; off >>= 1) {
        if (t < off) sm[t] += sm[t + off];
        __syncthreads();
    }
    if (t == 0) g_part[b] = sm[0];
    __syncthreads();

    if (b < 3) {
        const float* We = (b == 0) ? We0 : (b == 1) ? We1 : We2;
        const float* ae = (b == 0) ? ae0 : (b == 1) ? ae1 : ae2;
        sm[t] = (t < HID) ? We[t] * ae[t] : 0.f;
        __syncthreads();
        for (int off = 128; off > 0; off >>= 1) {
            if (t < off) sm[t] += sm[t + off];
            __syncthreads();
        }
        if (t == 0) g_scal[1 + b] = sm[0];
    }
}

// histogram over REAL edges only (self loops pre-counted), int4 loads
__global__ void k_hist(const int* __restrict__ eidx) {
    int q = blockIdx.x * blockDim.x + threadIdx.x;
    if (q >= NE / 4) return;
    int4 d4 = reinterpret_cast<const int4*>(eidx + NE)[q];
    atomicAdd(&g_cnt[d4.x], 1);
    atomicAdd(&g_cnt[d4.y], 1);
    atomicAdd(&g_cnt[d4.z], 1);
    atomicAdd(&g_cnt[d4.w], 1);
}

__global__ void k_s1() {
    __shared__ int sh[256];
    int t = threadIdx.x;
    int i = blockIdx.x * 256 + t;
    int v = (i < NN) ? g_cnt[i] : 0;
    sh[t] = v;
    __syncthreads();
    for (int off = 1; off < 256; off <<= 1) {
        int x = (t >= off) ? sh[t - off] : 0;
        __syncthreads();
        sh[t] += x;
        __syncthreads();
    }
    if (i < NN) {
        int r = sh[t] - v;
        g_rofs[i] = r;
        g_pos[i] = r;
    }
    if (t == 255) g_bsum[blockIdx.x] = sh[t];
}

__global__ void k_s2(int nb) {
    __shared__ int sh[256];
    __shared__ float sf[256];
    int t = threadIdx.x;
    int v = (t < nb) ? g_bsum[t] : 0;
    sh[t] = v;
    sf[t] = g_part[t] + g_part[t + 256];
    __syncthreads();
    for (int off = 1; off < 256; off <<= 1) {
        int x = (t >= off) ? sh[t - off] : 0;
        __syncthreads();
        sh[t] += x;
        __syncthreads();
    }
    if (t < nb) g_bpre[t] = sh[t] - v;
    for (int off = 128; off > 0; off >>= 1) {
        if (t < off) sf[t] += sf[t + off];
        __syncthreads();
    }
    if (t == 0) g_scal[0] = sf[0];
}

__global__ void k_scat(const int* __restrict__ eidx, const float* __restrict__ ew) {
    int e = blockIdx.x * blockDim.x + threadIdx.x;
    if (e >= ET) return;
    int s, d;
    float a;
    if (e < NE) {
        s = eidx[e];
        d = eidx[NE + e];
        a = ew[e];
    } else {
        s = d = e - NE;
        a = g_scal[0] * (1.0f / (float)NE);
    }
    int p = atomicAdd(&g_pos[d], 1) + g_bpre[d >> 8];
    g_edge[p] = make_int2(s, __float_as_int(a));
}

// ---------------- HMMA GEMM (wmma) + attention logits ----------------
#define LDA 136   // half
#define LDB 72    // half
#define LDC 68    // float

__global__ void k_gemm(const float* __restrict__ X, int ext, int Fin,
                       const float* __restrict__ W,
                       const float* __restrict__ bias_prev,
                       const float* __restrict__ as_, const float* __restrict__ ad_) {
    __shared__ __align__(16) char sbuf[18432 + 17408];
    __half* Bs = reinterpret_cast<__half*>(sbuf);            // [K][LDB]
    __half* As = reinterpret_cast<__half*>(sbuf + 18432);    // [64][LDA]
    float*  Cs = reinterpret_cast<float*>(sbuf + 18432);     // [64][LDC] alias

    int t = threadIdx.x;
    int w = t >> 5;
    int n0 = blockIdx.x * 64;

    if (ext) {
        int r = t >> 1;
        int n = n0 + r;
        const float4* xrow = reinterpret_cast<const float4*>(X + (size_t)n * FIN);
        #pragma unroll
        for (int f = 0; f < 16; f++) {
            int c4 = (t & 1) * 16 + f;
            float4 v = (n < NN) ? xrow[c4] : make_float4(0, 0, 0, 0);
            __half2* p = reinterpret_cast<__half2*>(&As[r * LDA + c4 * 4]);
            p[0] = __floats2half2_rn(v.x, v.y);
            p[1] = __floats2half2_rn(v.z, v.w);
        }
    } else {
        int r = t >> 1;
        int n = n0 + r;
        int cbase = (t & 1) * 32;
        #pragma unroll
        for (int c = 0; c < 16; c++) {
            int col = cbase + c * 2;
            float2 hv = {0.f, 0.f};
            if (n < NN)
                hv = __half22float2(*reinterpret_cast<const __half2*>(
                    &g_out[((size_t)n << 6) + col]));
            float bx = bias_prev[col], by = bias_prev[col + 1];
            hv.x = fmaxf(hv.x + bx, 0.f);
            hv.y = fmaxf(hv.y + by, 0.f);
            *reinterpret_cast<__half2*>(&As[r * LDA + col]) = __floats2half2_rn(hv.x, hv.y);
        }
    }

    {
        int total4 = Fin * HID / 4;
        const float4* w4 = reinterpret_cast<const float4*>(W);
        for (int idx = t; idx < total4; idx += 128) {
            int r = idx >> 4;
            int c4 = idx & 15;
            float4 v = w4[idx];
            __half2* p = reinterpret_cast<__half2*>(&Bs[r * LDB + c4 * 4]);
            p[0] = __floats2half2_rn(v.x, v.y);
            p[1] = __floats2half2_rn(v.z, v.w);
        }
    }
    __syncthreads();

    wmma::fragment<wmma::accumulator, 16, 16, 16, float> acc[4];
    #pragma unroll
    for (int nt = 0; nt < 4; nt++) wmma::fill_fragment(acc[nt], 0.f);

    int ksteps = Fin >> 4;
    for (int kt = 0; kt < ksteps; kt++) {
        wmma::fragment<wmma::matrix_a, 16, 16, 16, __half, wmma::row_major> af;
        wmma::load_matrix_sync(af, &As[(w * 16) * LDA + kt * 16], LDA);
        #pragma unroll
        for (int nt = 0; nt < 4; nt++) {
            wmma::fragment<wmma::matrix_b, 16, 16, 16, __half, wmma::row_major> bf;
            wmma::load_matrix_sync(bf, &Bs[(kt * 16) * LDB + nt * 16], LDB);
            wmma::mma_sync(acc[nt], af, bf, acc[nt]);
        }
    }
    __syncthreads();

    #pragma unroll
    for (int nt = 0; nt < 4; nt++)
        wmma::store_matrix_sync(&Cs[(w * 16) * LDC + nt * 16], acc[nt], LDC,
                                wmma::mem_row_major);
    __syncthreads();

    {
        int r = t >> 1;
        int n = n0 + r;
        int cbase = (t & 1) * 32;
        float s = 0.f, d = 0.f;
        if (n < NN) {
            #pragma unroll
            for (int c = 0; c < 32; c += 2) {
                int col = cbase + c;
                float v0 = Cs[r * LDC + col];
                float v1 = Cs[r * LDC + col + 1];
                *reinterpret_cast<__half2*>(&g_hh[((size_t)n << 6) + col]) =
                    __floats2half2_rn(v0, v1);
                s = fmaf(v0, as_[col], s); s = fmaf(v1, as_[col + 1], s);
                d = fmaf(v0, ad_[col], d); d = fmaf(v1, ad_[col + 1], d);
            }
        }
        s += __shfl_xor_sync(0xffffffffu, s, 1);
        d += __shfl_xor_sync(0xffffffffu, d, 1);
        if ((t & 1) == 0 && n < NN) {
            g_asrc[n] = s;
            g_adst[n] = d;
        }
    }
}

// ---------------- segmented aggregation: warp per dst node ----------------
__global__ void k_agg(int layer, const int* __restrict__ batch,
                      const float* __restrict__ bias_last) {
    int n = blockIdx.x * 8 + (threadIdx.x >> 5);
    int lane = threadIdx.x & 31;
    int start = g_rofs[n] + g_bpre[n >> 8];
    int n2 = n + 1;
    int end = (n2 == NN) ? ET : g_rofs[n2] + g_bpre[n2 >> 8];
    float c = g_scal[1 + layer];
    float adstn = g_adst[n];

    float accx = 0.f, accy = 0.f, ssum = 0.f;

    for (int base = start; base < end; base += 32) {
        int i = base + lane;
        int s_l = 0;
        float alpha = 0.f;
        if (i < end) {
            int2 ev = g_edge[i];
            s_l = ev.x;
            float al = g_asrc[s_l] + adstn + __int_as_float(ev.y) * c;
            al = fmaxf(al, 0.f) + SLOPE * fminf(al, 0.f);
            alpha = __expf(al);
        }
        ssum += alpha;
        int cnt = min(32, end - base);
        int jj = 0;
        for (; jj + 8 <= cnt; jj += 8) {
            __half2 hv[8];
            float aj[8];
            #pragma unroll
            for (int u = 0; u < 8; u++) {
                int sj = __shfl_sync(0xffffffffu, s_l, jj + u);
                aj[u]  = __shfl_sync(0xffffffffu, alpha, jj + u);
                hv[u] = *reinterpret_cast<const __half2*>(
                    &g_hh[((size_t)sj << 6) + (lane << 1)]);
            }
            #pragma unroll
            for (int u = 0; u < 8; u++) {
                float2 f = __half22float2(hv[u]);
                accx = fmaf(aj[u], f.x, accx);
                accy = fmaf(aj[u], f.y, accy);
            }
        }
        for (; jj < cnt; jj++) {
            int   sj = __shfl_sync(0xffffffffu, s_l, jj);
            float a2 = __shfl_sync(0xffffffffu, alpha, jj);
            float2 f = __half22float2(*reinterpret_cast<const __half2*>(
                &g_hh[((size_t)sj << 6) + (lane << 1)]));
            accx = fmaf(a2, f.x, accx);
            accy = fmaf(a2, f.y, accy);
        }
    }

    #pragma unroll
    for (int off = 16; off > 0; off >>= 1)
        ssum += __shfl_xor_sync(0xffffffffu, ssum, off);
    float inv = 1.f / (ssum + 1e-16f);
    float ox = accx * inv, oy = accy * inv;

    if (layer < 2) {
        *reinterpret_cast<__half2*>(&g_out[((size_t)n << 6) + (lane << 1)]) =
            __floats2half2_rn(ox, oy);
    } else {
        int g = batch[n];
        float2 bb = *reinterpret_cast<const float2*>(&bias_last[lane << 1]);
        float* p = &g_pooled[((size_t)g << 6) + (lane << 1)];
        asm volatile("red.global.add.v2.f32 [%0], {%1,%2};"
                     :: "l"(p), "f"(ox + bb.x), "f"(oy + bb.y) : "memory");
        if (lane == 0) atomicAdd(&g_gcnt[g], 1.f);
    }
}

// ---------------- readout ----------------
__global__ void k_read(const float* __restrict__ lin_w,
                       const float* __restrict__ lin_b, float* __restrict__ outp) {
    __shared__ float r[64];
    int g = blockIdx.x, j = threadIdx.x;
    float cnt = fmaxf(g_gcnt[g], 1.f);
    r[j] = (g_pooled[(size_t)g * HID + j] / cnt) * lin_w[j];
    __syncthreads();
    for (int off = 32; off > 0; off >>= 1) {
        if (j < off) r[j] += r[j + off];
        __syncthreads();
    }
    if (j == 0) {
        float v = r[0] + lin_b[0];
        outp[g] = 1.f / (1.f + expf(-v));
    }
}

// ---------------- stream/event resources (static init: before mem checkpoint) ----
static cudaStream_t g_stream2;
static cudaEvent_t  g_evFork, g_evJoin;
namespace {
struct InitRes {
    InitRes() {
        cudaStreamCreateWithFlags(&g_stream2, cudaStreamNonBlocking);
        cudaEventCreateWithFlags(&g_evFork, cudaEventDisableTiming);
        cudaEventCreateWithFlags(&g_evJoin, cudaEventDisableTiming);
    }
};
InitRes g_initres;
}

// ---------------- launch ----------------
extern "C" void kernel_launch(void* const* d_in, const int* in_sizes, int n_in,
                              void* d_out, int out_size) {
    const float* x     = (const float*)d_in[0];
    const int*   eidx  = (const int*)  d_in[1];
    const float* ew    = (const float*)d_in[2];
    const int*   batch = (const int*)  d_in[3];
    const float* W[3]  = {(const float*)d_in[4],  (const float*)d_in[10], (const float*)d_in[16]};
    const float* as_[3]= {(const float*)d_in[5],  (const float*)d_in[11], (const float*)d_in[17]};
    const float* ad_[3]= {(const float*)d_in[6],  (const float*)d_in[12], (const float*)d_in[18]};
    const float* We[3] = {(const float*)d_in[7],  (const float*)d_in[13], (const float*)d_in[19]};
    const float* ae[3] = {(const float*)d_in[8],  (const float*)d_in[14], (const float*)d_in[20]};
    const float* b[3]  = {(const float*)d_in[9],  (const float*)d_in[15], (const float*)d_in[21]};
    const float* lin_w = (const float*)d_in[22];
    const float* lin_b = (const float*)d_in[23];
    float* outp = (float*)d_out;

    const int NB_SCAN = (NN + 255) / 256;     // 196
    const int GEMM_BLOCKS = (NN + 63) / 64;   // 782
    const int WARP_BLOCKS = NN / 8;           // 6250

    // fork: layer-1 GEMM on stream2 (independent of the CSR-build chain)
    cudaEventRecord(g_evFork, 0);
    cudaStreamWaitEvent(g_stream2, g_evFork, 0);
    k_gemm<<<GEMM_BLOCKS, 128, 0, g_stream2>>>(x, 1, FIN, W[0], b[0], as_[0], ad_[0]);
    cudaEventRecord(g_evJoin, g_stream2);

    // CSR-build chain on the capture stream
    k_pre<<<PRE_BLOCKS, 256>>>(We[0], ae[0], We[1], ae[1], We[2], ae[2], ew);
    k_hist<<<(NE / 4 + 255) / 256, 256>>>(eidx);
    k_s1<<<NB_SCAN, 256>>>();
    k_s2<<<1, 256>>>(NB_SCAN);
    k_scat<<<(ET + 255) / 256, 256>>>(eidx, ew);

    // join: agg0 needs both gemm1 and the CSR
    cudaStreamWaitEvent(0, g_evJoin, 0);

    k_agg<<<WARP_BLOCKS, 256>>>(0, batch, b[2]);
    k_gemm<<<GEMM_BLOCKS, 128>>>(x, 0, HID, W[1], b[0], as_[1], ad_[1]);
    k_agg<<<WARP_BLOCKS, 256>>>(1, batch, b[2]);
    k_gemm<<<GEMM_BLOCKS, 128>>>(x, 0, HID, W[2], b[1], as_[2], ad_[2]);
    k_agg<<<WARP_BLOCKS, 256>>>(2, batch, b[2]);

    k_read<<<NG, 64>>>(lin_w, lin_b, outp);
}